// round 7
// baseline (speedup 1.0000x reference)
#include <cuda_runtime.h>

// SpatialMaxout2d forward, kh=kw=2, H=W=224. Padding windows fully cropped,
// so only the 112x112 in-bounds 2x2 windows matter.
//
// Per window (v0,v1,v2,v3 row-major), a[i] = alpha flat:
//   mx  = max(v); idx = first argmax
//   out[i] = (1-a[i]) * (i==idx ? mx : 0) + a[i]*v[i]
//
// R2: one thread = 8-wide x 2-tall patch (4 windows) via 4x float4 loads
// (MLP=4) + 4x float4 stores, to deepen the per-warp outstanding-load queue
// and push DRAM utilization toward the streaming ceiling.

__device__ __forceinline__ void blend_window(
    float v0, float v1, float v2, float v3,
    float a0, float a1, float a2, float a3,
    float& o0, float& o1, float& o2, float& o3)
{
    float mx = fmaxf(fmaxf(v0, v1), fmaxf(v2, v3));
    // first-argmax one-hot (jnp.argmax picks first max)
    bool m0 = (v0 == mx);
    bool m1 = (!m0) && (v1 == mx);
    bool m2 = (!m0) && (!m1) && (v2 == mx);
    bool m3 = (!m0) && (!m1) && (!m2);
    float u0 = m0 ? mx : 0.0f;
    float u1 = m1 ? mx : 0.0f;
    float u2 = m2 ? mx : 0.0f;
    float u3 = m3 ? mx : 0.0f;
    o0 = (1.0f - a0) * u0 + a0 * v0;
    o1 = (1.0f - a1) * u1 + a1 * v1;
    o2 = (1.0f - a2) * u2 + a2 * v2;
    o3 = (1.0f - a3) * u3 + a3 * v3;
}

__global__ void spatial_maxout2d_kernel(
    const float* __restrict__ x,
    const float* __restrict__ alpha,
    float* __restrict__ out,
    int total)   // total octo-tasks = B*C*112*28
{
    int t = blockIdx.x * blockDim.x + threadIdx.x;
    if (t >= total) return;

    const float a0 = __ldg(alpha + 0);
    const float a1 = __ldg(alpha + 1);
    const float a2 = __ldg(alpha + 2);
    const float a3 = __ldg(alpha + 3);

    // Decompose: wo in [0,28) octo-column, r in [0,112) window-row, bc plane
    int wo = t % 28;
    int tmp = t / 28;
    int r = tmp % 112;
    int bc = tmp / 112;

    // element offset of the top-left of this 8-wide patch
    long long base = (long long)bc * (224 * 224) + (long long)(2 * r) * 224 + 8 * wo;

    // Front-batch all four independent loads (MLP = 4)
    float4 r0a = *reinterpret_cast<const float4*>(x + base);
    float4 r0b = *reinterpret_cast<const float4*>(x + base + 4);
    float4 r1a = *reinterpret_cast<const float4*>(x + base + 224);
    float4 r1b = *reinterpret_cast<const float4*>(x + base + 228);

    float4 o0a, o0b, o1a, o1b;

    blend_window(r0a.x, r0a.y, r1a.x, r1a.y, a0, a1, a2, a3,
                 o0a.x, o0a.y, o1a.x, o1a.y);
    blend_window(r0a.z, r0a.w, r1a.z, r1a.w, a0, a1, a2, a3,
                 o0a.z, o0a.w, o1a.z, o1a.w);
    blend_window(r0b.x, r0b.y, r1b.x, r1b.y, a0, a1, a2, a3,
                 o0b.x, o0b.y, o1b.x, o1b.y);
    blend_window(r0b.z, r0b.w, r1b.z, r1b.w, a0, a1, a2, a3,
                 o0b.z, o0b.w, o1b.z, o1b.w);

    *reinterpret_cast<float4*>(out + base)       = o0a;
    *reinterpret_cast<float4*>(out + base + 4)   = o0b;
    *reinterpret_cast<float4*>(out + base + 224) = o1a;
    *reinterpret_cast<float4*>(out + base + 228) = o1b;
}

extern "C" void kernel_launch(void* const* d_in, const int* in_sizes, int n_in,
                              void* d_out, int out_size)
{
    const float* x     = (const float*)d_in[0];
    const float* alpha = (const float*)d_in[1];
    float* out = (float*)d_out;

    // B*C = 2048 planes; per plane 112 window-rows x 28 octo-cols
    const int total = 2048 * 112 * 28;   // 6,422,528
    const int threads = 256;
    const int blocks = (total + threads - 1) / threads;  // 25088

    spatial_maxout2d_kernel<<<blocks, threads>>>(x, alpha, out, total);
}

// round 10
// speedup vs baseline: 1.0878x; 1.0878x over previous
#include <cuda_runtime.h>

// SpatialMaxout2d forward, kh=kw=2, H=W=224. Padding windows fully cropped,
// so only the 112x112 in-bounds 2x2 windows matter.
//
// Per window (v0,v1,v2,v3 row-major), a[i] = alpha flat:
//   mx  = max(v); idx = first argmax
//   out[i] = (1-a[i]) * (i==idx ? mx : 0) + a[i]*v[i]
//
// R8: one thread = 4-wide x 4-tall patch (2 windows in one column-pair,
// spanning two window-rows). 4 front-batched float4 loads (MLP=4), each
// VERTICALLY stacked so every LDG.128 stays warp-contiguous (lane stride
// 16B -> 512B contiguous per warp-load, same per-instruction efficiency
// as the R1 baseline). Fixes the R2 regression where 8-wide tiles made
// lanes 32B apart and fragmented sectors.

__device__ __forceinline__ void blend_window(
    float v0, float v1, float v2, float v3,
    float a0, float a1, float a2, float a3,
    float& o0, float& o1, float& o2, float& o3)
{
    float mx = fmaxf(fmaxf(v0, v1), fmaxf(v2, v3));
    // first-argmax one-hot (jnp.argmax picks first max)
    bool m0 = (v0 == mx);
    bool m1 = (!m0) && (v1 == mx);
    bool m2 = (!m0) && (!m1) && (v2 == mx);
    bool m3 = (!m0) && (!m1) && (!m2);
    float u0 = m0 ? mx : 0.0f;
    float u1 = m1 ? mx : 0.0f;
    float u2 = m2 ? mx : 0.0f;
    float u3 = m3 ? mx : 0.0f;
    o0 = (1.0f - a0) * u0 + a0 * v0;
    o1 = (1.0f - a1) * u1 + a1 * v1;
    o2 = (1.0f - a2) * u2 + a2 * v2;
    o3 = (1.0f - a3) * u3 + a3 * v3;
}

__global__ void spatial_maxout2d_kernel(
    const float* __restrict__ x,
    const float* __restrict__ alpha,
    float* __restrict__ out,
    int total)   // total tasks = B*C*56*56
{
    int t = blockIdx.x * blockDim.x + threadIdx.x;
    if (t >= total) return;

    const float a0 = __ldg(alpha + 0);
    const float a1 = __ldg(alpha + 1);
    const float a2 = __ldg(alpha + 2);
    const float a3 = __ldg(alpha + 3);

    // Decompose: wq in [0,56) quad-column, rp in [0,56) window-row-pair, bc plane
    int wq = t % 56;
    int tmp = t / 56;
    int rp = tmp % 56;
    int bc = tmp / 56;

    // element offset of the top-left of this 4-wide x 4-tall patch
    long long base = (long long)bc * (224 * 224) + (long long)(4 * rp) * 224 + 4 * wq;

    // Front-batch 4 independent, warp-contiguous loads (MLP = 4)
    float4 r0 = *reinterpret_cast<const float4*>(x + base);
    float4 r1 = *reinterpret_cast<const float4*>(x + base + 224);
    float4 r2 = *reinterpret_cast<const float4*>(x + base + 448);
    float4 r3 = *reinterpret_cast<const float4*>(x + base + 672);

    float4 o0, o1;

    // window-row A (image rows 0,1 of patch): windows (cols 0,1) and (cols 2,3)
    blend_window(r0.x, r0.y, r1.x, r1.y, a0, a1, a2, a3,
                 o0.x, o0.y, o1.x, o1.y);
    blend_window(r0.z, r0.w, r1.z, r1.w, a0, a1, a2, a3,
                 o0.z, o0.w, o1.z, o1.w);
    *reinterpret_cast<float4*>(out + base)       = o0;
    *reinterpret_cast<float4*>(out + base + 224) = o1;

    // window-row B (image rows 2,3 of patch)
    blend_window(r2.x, r2.y, r3.x, r3.y, a0, a1, a2, a3,
                 o0.x, o0.y, o1.x, o1.y);
    blend_window(r2.z, r2.w, r3.z, r3.w, a0, a1, a2, a3,
                 o0.z, o0.w, o1.z, o1.w);
    *reinterpret_cast<float4*>(out + base + 448) = o0;
    *reinterpret_cast<float4*>(out + base + 672) = o1;
}

extern "C" void kernel_launch(void* const* d_in, const int* in_sizes, int n_in,
                              void* d_out, int out_size)
{
    const float* x     = (const float*)d_in[0];
    const float* alpha = (const float*)d_in[1];
    float* out = (float*)d_out;

    // B*C = 2048 planes; per plane 56 window-row-pairs x 56 quad-cols
    const int total = 2048 * 56 * 56;   // 6,422,528
    const int threads = 256;
    const int blocks = (total + threads - 1) / threads;  // 25088

    spatial_maxout2d_kernel<<<blocks, threads>>>(x, alpha, out, total);
}

// round 12
// speedup vs baseline: 1.0973x; 1.0087x over previous
#include <cuda_runtime.h>

// SpatialMaxout2d forward, kh=kw=2, H=W=224. Padding windows fully cropped,
// so only the 112x112 in-bounds 2x2 windows matter.
//
// Per window (v0,v1,v2,v3 row-major), a[i] = alpha flat:
//   mx  = max(v); idx = first argmax
//   out[i] = (1-a[i]) * (i==idx ? mx : 0) + a[i]*v[i]
//
// R11: R8 structure (4-wide x 4-tall patch, 4 warp-contiguous front-batched
// float4 loads) + streaming cache hints: __ldcs on x, __stcs on out.
// Both streams are touched exactly once -> evict-first policy reduces L2
// retention pressure on a pure streaming kernel.

__device__ __forceinline__ void blend_window(
    float v0, float v1, float v2, float v3,
    float a0, float a1, float a2, float a3,
    float& o0, float& o1, float& o2, float& o3)
{
    float mx = fmaxf(fmaxf(v0, v1), fmaxf(v2, v3));
    // first-argmax one-hot (jnp.argmax picks first max)
    bool m0 = (v0 == mx);
    bool m1 = (!m0) && (v1 == mx);
    bool m2 = (!m0) && (!m1) && (v2 == mx);
    bool m3 = (!m0) && (!m1) && (!m2);
    float u0 = m0 ? mx : 0.0f;
    float u1 = m1 ? mx : 0.0f;
    float u2 = m2 ? mx : 0.0f;
    float u3 = m3 ? mx : 0.0f;
    o0 = (1.0f - a0) * u0 + a0 * v0;
    o1 = (1.0f - a1) * u1 + a1 * v1;
    o2 = (1.0f - a2) * u2 + a2 * v2;
    o3 = (1.0f - a3) * u3 + a3 * v3;
}

__global__ void spatial_maxout2d_kernel(
    const float* __restrict__ x,
    const float* __restrict__ alpha,
    float* __restrict__ out,
    int total)   // total tasks = B*C*56*56
{
    int t = blockIdx.x * blockDim.x + threadIdx.x;
    if (t >= total) return;

    const float a0 = __ldg(alpha + 0);
    const float a1 = __ldg(alpha + 1);
    const float a2 = __ldg(alpha + 2);
    const float a3 = __ldg(alpha + 3);

    // Decompose: wq in [0,56) quad-column, rp in [0,56) window-row-pair, bc plane
    int wq = t % 56;
    int tmp = t / 56;
    int rp = tmp % 56;
    int bc = tmp / 56;

    // element offset of the top-left of this 4-wide x 4-tall patch
    long long base = (long long)bc * (224 * 224) + (long long)(4 * rp) * 224 + 4 * wq;

    // Front-batch 4 independent, warp-contiguous streaming loads (MLP = 4)
    float4 r0 = __ldcs(reinterpret_cast<const float4*>(x + base));
    float4 r1 = __ldcs(reinterpret_cast<const float4*>(x + base + 224));
    float4 r2 = __ldcs(reinterpret_cast<const float4*>(x + base + 448));
    float4 r3 = __ldcs(reinterpret_cast<const float4*>(x + base + 672));

    float4 o0, o1;

    // window-row A (image rows 0,1 of patch): windows (cols 0,1) and (cols 2,3)
    blend_window(r0.x, r0.y, r1.x, r1.y, a0, a1, a2, a3,
                 o0.x, o0.y, o1.x, o1.y);
    blend_window(r0.z, r0.w, r1.z, r1.w, a0, a1, a2, a3,
                 o0.z, o0.w, o1.z, o1.w);
    __stcs(reinterpret_cast<float4*>(out + base),       o0);
    __stcs(reinterpret_cast<float4*>(out + base + 224), o1);

    // window-row B (image rows 2,3 of patch)
    blend_window(r2.x, r2.y, r3.x, r3.y, a0, a1, a2, a3,
                 o0.x, o0.y, o1.x, o1.y);
    blend_window(r2.z, r2.w, r3.z, r3.w, a0, a1, a2, a3,
                 o0.z, o0.w, o1.z, o1.w);
    __stcs(reinterpret_cast<float4*>(out + base + 448), o0);
    __stcs(reinterpret_cast<float4*>(out + base + 672), o1);
}

extern "C" void kernel_launch(void* const* d_in, const int* in_sizes, int n_in,
                              void* d_out, int out_size)
{
    const float* x     = (const float*)d_in[0];
    const float* alpha = (const float*)d_in[1];
    float* out = (float*)d_out;

    // B*C = 2048 planes; per plane 56 window-row-pairs x 56 quad-cols
    const int total = 2048 * 56 * 56;   // 6,422,528
    const int threads = 256;
    const int blocks = (total + threads - 1) / threads;  // 25088

    spatial_maxout2d_kernel<<<blocks, threads>>>(x, alpha, out, total);
}